// round 2
// baseline (speedup 1.0000x reference)
#include <cuda_runtime.h>
#include <cuda_bf16.h>
#include <cstdint>

#define M_TOTAL 8192
#define IN_F    4096
#define OUT_F   4096
#define RANK    64

// ---------------- device scratch (16B aligned for vector ld/st) ----------------
__device__ __align__(16) __nv_bfloat16 g_Vt_hi[RANK * IN_F];   // [64][4096] K-major
__device__ __align__(16) __nv_bfloat16 g_Vt_lo[RANK * IN_F];
__device__ __align__(16) __nv_bfloat16 g_U_hi[OUT_F * RANK];   // [4096][64] K-major
__device__ __align__(16) __nv_bfloat16 g_U_lo[OUT_F * RANK];
__device__ __align__(16) __nv_bfloat16 g_T_hi[M_TOTAL * RANK]; // [8192][64]
__device__ __align__(16) __nv_bfloat16 g_T_lo[M_TOTAL * RANK];

// ---------------- helpers ----------------
__device__ __forceinline__ uint32_t smem_u32(const void* p) {
    uint32_t a;
    asm("{ .reg .u64 t; cvta.to.shared.u64 t, %1; cvt.u32.u64 %0, t; }" : "=r"(a) : "l"(p));
    return a;
}
#define SWZ(o) ((o) ^ (((o) >> 3) & 0x70))

__device__ __forceinline__ void ldmx4(uint32_t* r, uint32_t addr) {
    asm volatile("ldmatrix.sync.aligned.m8n8.x4.shared.b16 {%0,%1,%2,%3}, [%4];"
                 : "=r"(r[0]), "=r"(r[1]), "=r"(r[2]), "=r"(r[3]) : "r"(addr));
}
__device__ __forceinline__ void mma_bf16(float* d, const uint32_t* a, const uint32_t* b) {
    asm volatile(
        "mma.sync.aligned.m16n8k16.row.col.f32.bf16.bf16.f32 "
        "{%0,%1,%2,%3}, {%4,%5,%6,%7}, {%8,%9}, {%0,%1,%2,%3};"
        : "+f"(d[0]), "+f"(d[1]), "+f"(d[2]), "+f"(d[3])
        : "r"(a[0]), "r"(a[1]), "r"(a[2]), "r"(a[3]), "r"(b[0]), "r"(b[1]));
}
__device__ __forceinline__ uint32_t pack_bf2(float a, float b) {
    __nv_bfloat162 h = __floats2bfloat162_rn(a, b);
    return *(uint32_t*)&h;
}

// ========================================================================
// Kernel 0: split U, V into bf16 hi/lo; transpose V -> [RANK][IN_F]
// ========================================================================
__global__ void __launch_bounds__(256) k0_prep(const float* __restrict__ U,
                                               const float* __restrict__ V) {
    int i = blockIdx.x * 256 + threadIdx.x;
    if (i >= OUT_F * RANK) return;
    {
        float u = U[i];
        __nv_bfloat16 uh = __float2bfloat16(u);
        g_U_hi[i] = uh;
        g_U_lo[i] = __float2bfloat16(u - __bfloat162float(uh));
    }
    {
        float v = V[i];          // V[k][r], k = i/64, r = i%64
        int k = i >> 6;
        int r = i & 63;
        __nv_bfloat16 vh = __float2bfloat16(v);
        g_Vt_hi[r * IN_F + k] = vh;
        g_Vt_lo[r * IN_F + k] = __float2bfloat16(v - __bfloat162float(vh));
    }
}

// ========================================================================
// Kernel 1: T = x @ V    CTA tile [64 M][64 N], K = 4096, grid 128
// 8 warps, warp tile 16 M x 32 N. bf16 hi/lo 3-product split. HMMA.
// ========================================================================
static constexpr int S1_AHI = 0, S1_ALO = 8192, S1_BHI = 16384, S1_BLO = 24576;
static constexpr int S1_STAGE = 32768;
static constexpr int SM1_TOTAL = 2 * S1_STAGE;   // 65536

__global__ void __launch_bounds__(256) k1_gemm1(const float* __restrict__ x) {
    extern __shared__ char smem[];
    const uint32_t sb = smem_u32(smem);
    const int tid  = threadIdx.x;
    const int lane = tid & 31;
    const int wid  = tid >> 5;
    const int wm   = wid >> 1;       // 0..3  (16-row slabs)
    const int wn   = wid & 1;        // 0..1  (32-col slabs)
    const int m0   = blockIdx.x * 64;

    const int sub = lane >> 3, lr = lane & 7;
    // ldmatrix per-lane row offsets (col part added per k-step)
    const uint32_t a_off  = (uint32_t)((wm * 16 + (sub & 1) * 8 + lr) * 128 + (sub >> 1) * 16);
    const uint32_t b_off0 = (uint32_t)((wn * 32 + (sub >> 1) * 8 + lr) * 128 + (sub & 1) * 16);
    const uint32_t b_off1 = b_off0 + 16 * 128;

    float acc[4][4];
    #pragma unroll
    for (int j = 0; j < 4; j++)
        #pragma unroll
        for (int t = 0; t < 4; t++) acc[j][t] = 0.0f;

    const float* xs = x + (size_t)m0 * IN_F;

    float4 xa[4];
    uint4  vh[2], vl[2];

    auto load_x = [&](int c) {
        #pragma unroll
        for (int i = 0; i < 4; i++) {
            int idx = tid + i * 256;          // 0..1023
            int r = idx >> 4, q = idx & 15;   // 64 rows x 16 float4
            xa[i] = __ldg((const float4*)(xs + (size_t)r * IN_F + c * 64 + q * 4));
        }
    };
    auto store_x = [&](int buf) {
        char* st = smem + buf * S1_STAGE;
        #pragma unroll
        for (int i = 0; i < 4; i++) {
            int idx = tid + i * 256;
            int r = idx >> 4, q = idx & 15;
            float4 v = xa[i];
            __nv_bfloat162 h01 = __floats2bfloat162_rn(v.x, v.y);
            __nv_bfloat162 h23 = __floats2bfloat162_rn(v.z, v.w);
            float2 hf01 = __bfloat1622float2(h01);
            float2 hf23 = __bfloat1622float2(h23);
            __nv_bfloat162 l01 = __floats2bfloat162_rn(v.x - hf01.x, v.y - hf01.y);
            __nv_bfloat162 l23 = __floats2bfloat162_rn(v.z - hf23.x, v.w - hf23.y);
            uint32_t sw = SWZ((uint32_t)(r * 128 + q * 8));
            *(uint2*)(st + S1_AHI + sw) = make_uint2(*(uint32_t*)&h01, *(uint32_t*)&h23);
            *(uint2*)(st + S1_ALO + sw) = make_uint2(*(uint32_t*)&l01, *(uint32_t*)&l23);
        }
    };
    auto load_v = [&](int c) {
        #pragma unroll
        for (int i = 0; i < 2; i++) {
            int idx = tid + i * 256;          // 0..511
            int r = idx >> 3, q = idx & 7;    // 64 rows x 8 uint4
            size_t goff = (size_t)r * (IN_F * 2) + (size_t)c * 128 + q * 16;
            vh[i] = *(const uint4*)((const char*)g_Vt_hi + goff);
            vl[i] = *(const uint4*)((const char*)g_Vt_lo + goff);
        }
    };
    auto store_v = [&](int buf) {
        char* st = smem + buf * S1_STAGE;
        #pragma unroll
        for (int i = 0; i < 2; i++) {
            int idx = tid + i * 256;
            int r = idx >> 3, q = idx & 7;
            uint32_t sw = SWZ((uint32_t)(r * 128 + q * 16));
            *(uint4*)(st + S1_BHI + sw) = vh[i];
            *(uint4*)(st + S1_BLO + sw) = vl[i];
        }
    };

    load_x(0); load_v(0);
    store_x(0); store_v(0);
    __syncthreads();

    const int NCHUNK = IN_F / 64;    // 64
    for (int c = 0; c < NCHUNK; c++) {
        const int buf = c & 1;
        if (c + 1 < NCHUNK) { load_x(c + 1); load_v(c + 1); }

        const uint32_t sbuf = sb + buf * S1_STAGE;
        #pragma unroll
        for (int ks = 0; ks < 4; ks++) {
            uint32_t ah[4], al[4], bh[8], bl[8];
            uint32_t ka  = SWZ(a_off  + ks * 32);
            uint32_t kb0 = SWZ(b_off0 + ks * 32);
            uint32_t kb1 = SWZ(b_off1 + ks * 32);
            ldmx4(ah,     sbuf + S1_AHI + ka);
            ldmx4(al,     sbuf + S1_ALO + ka);
            ldmx4(bh,     sbuf + S1_BHI + kb0);
            ldmx4(bh + 4, sbuf + S1_BHI + kb1);
            ldmx4(bl,     sbuf + S1_BLO + kb0);
            ldmx4(bl + 4, sbuf + S1_BLO + kb1);
            #pragma unroll
            for (int j = 0; j < 4; j++) {
                mma_bf16(acc[j], ah, bh + 2 * j);
                mma_bf16(acc[j], ah, bl + 2 * j);
                mma_bf16(acc[j], al, bh + 2 * j);
            }
        }

        if (c + 1 < NCHUNK) { store_x((c + 1) & 1); store_v((c + 1) & 1); }
        __syncthreads();
    }

    // ---- epilogue: acc -> bf16 hi/lo -> g_T ----
    const int g = lane >> 2, tig = lane & 3;
    #pragma unroll
    for (int j = 0; j < 4; j++) {
        int col  = wn * 32 + j * 8 + tig * 2;
        int row0 = m0 + wm * 16 + g;
        // rows row0 (c0,c1) and row0+8 (c2,c3)
        #pragma unroll
        for (int h = 0; h < 2; h++) {
            int row = row0 + h * 8;
            float f0 = acc[j][2 * h], f1 = acc[j][2 * h + 1];
            __nv_bfloat16 h0 = __float2bfloat16(f0);
            __nv_bfloat16 h1 = __float2bfloat16(f1);
            float r0 = f0 - __bfloat162float(h0);
            float r1 = f1 - __bfloat162float(h1);
            __nv_bfloat162 hp = __halves2bfloat162(h0, h1);
            *(__nv_bfloat162*)(g_T_hi + (size_t)row * RANK + col) = hp;
            *(__nv_bfloat162*)(g_T_lo + (size_t)row * RANK + col) =
                __floats2bfloat162_rn(r0, r1);
        }
    }
}

// ========================================================================
// Kernel 2: y = T @ U^T + bias   CTA tile [128 M][128 N], K = 64
// grid 64*32 = 2048, 8 warps, warp tile 32 M x 64 N.
// ========================================================================
static constexpr int SM2_THI  = 0;
static constexpr int SM2_TLO  = 16384;
static constexpr int SM2_UHI  = 32768;
static constexpr int SM2_ULO  = 49152;
static constexpr int SM2_BIAS = 65536;
static constexpr int SM2_TOTAL = 65536 + 512;

__global__ void __launch_bounds__(256) k2_gemm2(const float* __restrict__ bias,
                                                float* __restrict__ y) {
    extern __shared__ char smem[];
    const uint32_t sb = smem_u32(smem);
    const int tid  = threadIdx.x;
    const int lane = tid & 31;
    const int wid  = tid >> 5;
    const int wm   = wid >> 1;       // 0..3 (32-row slabs)
    const int wn   = wid & 1;        // 0..1 (64-col slabs)
    const int m0   = (blockIdx.x >> 5) * 128;
    const int n0   = (blockIdx.x & 31) * 128;

    // ---- load T and U tiles [128][64] bf16 hi/lo ----
    #pragma unroll
    for (int i = 0; i < 4; i++) {
        int idx = tid + i * 256;          // 0..1023
        int r = idx >> 3, q = idx & 7;    // 128 rows x 8 uint4
        uint32_t sw = SWZ((uint32_t)(r * 128 + q * 16));
        size_t toff = (size_t)(m0 + r) * 128 + q * 16;
        *(uint4*)(smem + SM2_THI + sw) = *(const uint4*)((const char*)g_T_hi + toff);
        *(uint4*)(smem + SM2_TLO + sw) = *(const uint4*)((const char*)g_T_lo + toff);
        size_t uoff = (size_t)(n0 + r) * 128 + q * 16;
        *(uint4*)(smem + SM2_UHI + sw) = *(const uint4*)((const char*)g_U_hi + uoff);
        *(uint4*)(smem + SM2_ULO + sw) = *(const uint4*)((const char*)g_U_lo + uoff);
    }
    if (tid < 128) ((float*)(smem + SM2_BIAS))[tid] = bias[n0 + tid];
    __syncthreads();

    const int sub = lane >> 3, lr = lane & 7;
    uint32_t a_off[2], b_off[4];
    #pragma unroll
    for (int mt = 0; mt < 2; mt++)
        a_off[mt] = (uint32_t)((wm * 32 + mt * 16 + (sub & 1) * 8 + lr) * 128 + (sub >> 1) * 16);
    #pragma unroll
    for (int p = 0; p < 4; p++)
        b_off[p] = (uint32_t)((wn * 64 + (p * 2 + (sub >> 1)) * 8 + lr) * 128 + (sub & 1) * 16);

    float acc[2][8][4];
    #pragma unroll
    for (int mt = 0; mt < 2; mt++)
        #pragma unroll
        for (int j = 0; j < 8; j++)
            #pragma unroll
            for (int t = 0; t < 4; t++) acc[mt][j][t] = 0.0f;

    #pragma unroll
    for (int ks = 0; ks < 4; ks++) {
        uint32_t ah[2][4], al[2][4], bh[16], bl[16];
        #pragma unroll
        for (int mt = 0; mt < 2; mt++) {
            uint32_t ka = SWZ(a_off[mt] + ks * 32);
            ldmx4(ah[mt], sb + SM2_THI + ka);
            ldmx4(al[mt], sb + SM2_TLO + ka);
        }
        #pragma unroll
        for (int p = 0; p < 4; p++) {
            uint32_t kb = SWZ(b_off[p] + ks * 32);
            ldmx4(bh + 4 * p, sb + SM2_UHI + kb);
            ldmx4(bl + 4 * p, sb + SM2_ULO + kb);
        }
        #pragma unroll
        for (int mt = 0; mt < 2; mt++)
            #pragma unroll
            for (int j = 0; j < 8; j++) {
                mma_bf16(acc[mt][j], ah[mt], bh + 2 * j);
                mma_bf16(acc[mt][j], ah[mt], bl + 2 * j);
                mma_bf16(acc[mt][j], al[mt], bh + 2 * j);
            }
    }

    // ---- epilogue: +bias, direct STG.64 (8 full 32B sectors per store) ----
    const int g = lane >> 2, tig = lane & 3;
    const float* sbias = (const float*)(smem + SM2_BIAS);
    #pragma unroll
    for (int mt = 0; mt < 2; mt++) {
        #pragma unroll
        for (int j = 0; j < 8; j++) {
            int colr = wn * 64 + j * 8 + tig * 2;
            float b0 = sbias[colr], b1 = sbias[colr + 1];
            int row = m0 + wm * 32 + mt * 16 + g;
            float2 v0 = make_float2(acc[mt][j][0] + b0, acc[mt][j][1] + b1);
            float2 v1 = make_float2(acc[mt][j][2] + b0, acc[mt][j][3] + b1);
            *(float2*)(y + (size_t)row * OUT_F + n0 + colr)       = v0;
            *(float2*)(y + (size_t)(row + 8) * OUT_F + n0 + colr) = v1;
        }
    }
}

// ========================================================================
// launch
// ========================================================================
extern "C" void kernel_launch(void* const* d_in, const int* in_sizes, int n_in,
                              void* d_out, int out_size) {
    const float* x    = (const float*)d_in[0];
    const float* U    = (const float*)d_in[1];
    const float* V    = (const float*)d_in[2];
    const float* bias = (const float*)d_in[3];
    float* y = (float*)d_out;

    cudaFuncSetAttribute(k1_gemm1, cudaFuncAttributeMaxDynamicSharedMemorySize, SM1_TOTAL);
    cudaFuncSetAttribute(k2_gemm2, cudaFuncAttributeMaxDynamicSharedMemorySize, SM2_TOTAL);

    k0_prep<<<(OUT_F * RANK + 255) / 256, 256>>>(U, V);
    k1_gemm1<<<M_TOTAL / 64, 256, SM1_TOTAL>>>(x);
    k2_gemm2<<<(M_TOTAL / 128) * (OUT_F / 128), 256, SM2_TOTAL>>>(bias, y);
}

// round 3
// speedup vs baseline: 1.0875x; 1.0875x over previous
#include <cuda_runtime.h>
#include <cuda_fp16.h>
#include <cstdint>

#define M_TOTAL 8192
#define IN_F    4096
#define OUT_F   4096
#define RANK    64

// ---------------- device scratch ----------------
__device__ __align__(16) float g_T[M_TOTAL * RANK];   // [8192][64] f32

// ---------------- helpers ----------------
__device__ __forceinline__ uint32_t smem_u32(const void* p) {
    uint32_t a;
    asm("{ .reg .u64 t; cvta.to.shared.u64 t, %1; cvt.u32.u64 %0, t; }" : "=r"(a) : "l"(p));
    return a;
}
#define SWZ(o) ((o) ^ (((o) >> 3) & 0x70))

__device__ __forceinline__ void ldmx4(uint32_t* r, uint32_t addr) {
    asm volatile("ldmatrix.sync.aligned.m8n8.x4.shared.b16 {%0,%1,%2,%3}, [%4];"
                 : "=r"(r[0]), "=r"(r[1]), "=r"(r[2]), "=r"(r[3]) : "r"(addr));
}
__device__ __forceinline__ void ldmx4t(uint32_t* r, uint32_t addr) {
    asm volatile("ldmatrix.sync.aligned.m8n8.x4.trans.shared.b16 {%0,%1,%2,%3}, [%4];"
                 : "=r"(r[0]), "=r"(r[1]), "=r"(r[2]), "=r"(r[3]) : "r"(addr));
}
__device__ __forceinline__ void mma_f16(float* d, const uint32_t* a, const uint32_t* b) {
    asm volatile(
        "mma.sync.aligned.m16n8k16.row.col.f32.f16.f16.f32 "
        "{%0,%1,%2,%3}, {%4,%5,%6,%7}, {%8,%9}, {%0,%1,%2,%3};"
        : "+f"(d[0]), "+f"(d[1]), "+f"(d[2]), "+f"(d[3])
        : "r"(a[0]), "r"(a[1]), "r"(a[2]), "r"(a[3]), "r"(b[0]), "r"(b[1]));
}

// pack 8 floats -> 8 fp16 (uint4)
__device__ __forceinline__ uint4 pack8h(const float4& a, const float4& b) {
    __half2 h0 = __floats2half2_rn(a.x, a.y);
    __half2 h1 = __floats2half2_rn(a.z, a.w);
    __half2 h2 = __floats2half2_rn(b.x, b.y);
    __half2 h3 = __floats2half2_rn(b.z, b.w);
    return make_uint4(*(uint32_t*)&h0, *(uint32_t*)&h1, *(uint32_t*)&h2, *(uint32_t*)&h3);
}
// hi/lo split of 8 floats
__device__ __forceinline__ void split8h(const float4& a, const float4& b,
                                        uint4& hi, uint4& lo) {
    hi = pack8h(a, b);
    const __half* hp = (const __half*)&hi;
    float4 ra = make_float4(a.x - __half2float(hp[0]), a.y - __half2float(hp[1]),
                            a.z - __half2float(hp[2]), a.w - __half2float(hp[3]));
    float4 rb = make_float4(b.x - __half2float(hp[4]), b.y - __half2float(hp[5]),
                            b.z - __half2float(hp[6]), b.w - __half2float(hp[7]));
    lo = pack8h(ra, rb);
}

// ========================================================================
// Kernel 1: T = x @ V   CTA tile [64 M][64 N], K=4096, grid 128, 8 warps
// x split fp16 hi/lo (2 products), V single fp16 via ldmatrix.trans.
// ========================================================================
static constexpr int S1_AHI = 0, S1_ALO = 8192, S1_B = 16384;
static constexpr int S1_STAGE = 24576;
static constexpr int SM1_TOTAL = 2 * S1_STAGE;   // 49152

__global__ void __launch_bounds__(256) k1_gemm1(const float* __restrict__ x,
                                                const float* __restrict__ V) {
    extern __shared__ char smem[];
    const uint32_t sb = smem_u32(smem);
    const int tid  = threadIdx.x;
    const int lane = tid & 31;
    const int wid  = tid >> 5;
    const int wm   = wid >> 1;     // 0..3  (16-row slabs)
    const int wn   = wid & 1;      // 0..1  (32-col slabs)
    const int m0   = blockIdx.x * 64;

    const int sub = lane >> 3, lr = lane & 7;
    // A (x) fragments: [m][k] row-major, normal ldmatrix
    const uint32_t a_off = (uint32_t)((wm * 16 + (sub & 1) * 8 + lr) * 128 + (sub >> 1) * 16);
    // B (V) fragments: smem [k][n], ldmatrix.trans.
    // lane row = k = (sub&1)*8 + lr ; n-col byte off = (sub>>1)*16
    const uint32_t bt_row = (uint32_t)(((sub & 1) * 8 + lr) * 128 + (sub >> 1) * 16);
    const uint32_t bt_n0  = (uint32_t)(wn * 64);      // warp n-base in bytes

    float acc[4][4];
    #pragma unroll
    for (int j = 0; j < 4; j++)
        #pragma unroll
        for (int t = 0; t < 4; t++) acc[j][t] = 0.0f;

    const float* xs = x + (size_t)m0 * IN_F;

    float4 xa[2][2], va[2][2];

    auto load_g = [&](int c) {
        #pragma unroll
        for (int i = 0; i < 2; i++) {
            int idx = tid + i * 256;           // 0..511
            int r = idx >> 3, g = idx & 7;     // 64 rows x 8 groups(8 floats)
            const float* xp = xs + (size_t)r * IN_F + c * 64 + g * 8;
            xa[i][0] = __ldg((const float4*)xp);
            xa[i][1] = __ldg((const float4*)(xp + 4));
            const float* vp = V + (size_t)(c * 64 + r) * RANK + g * 8;
            va[i][0] = __ldg((const float4*)vp);
            va[i][1] = __ldg((const float4*)(vp + 4));
        }
    };
    auto store_s = [&](int buf) {
        char* st = smem + buf * S1_STAGE;
        #pragma unroll
        for (int i = 0; i < 2; i++) {
            int idx = tid + i * 256;
            int r = idx >> 3, g = idx & 7;
            uint32_t sw = SWZ((uint32_t)(r * 128 + g * 16));
            uint4 hi, lo;
            split8h(xa[i][0], xa[i][1], hi, lo);
            *(uint4*)(st + S1_AHI + sw) = hi;
            *(uint4*)(st + S1_ALO + sw) = lo;
            *(uint4*)(st + S1_B + sw) = pack8h(va[i][0], va[i][1]);
        }
    };

    load_g(0);
    store_s(0);
    __syncthreads();

    const int NCHUNK = IN_F / 64;    // 64
    for (int c = 0; c < NCHUNK; c++) {
        const int buf = c & 1;
        if (c + 1 < NCHUNK) load_g(c + 1);

        const uint32_t sbuf = sb + buf * S1_STAGE;
        #pragma unroll
        for (int ks = 0; ks < 4; ks++) {
            uint32_t ah[4], al[4], b[8];
            uint32_t ka = SWZ(a_off + ks * 32);
            ldmx4(ah, sbuf + S1_AHI + ka);
            ldmx4(al, sbuf + S1_ALO + ka);
            #pragma unroll
            for (int g = 0; g < 2; g++) {
                uint32_t kb = SWZ(bt_row + ks * 16 * 128 + bt_n0 + g * 32);
                ldmx4t(b + 4 * g, sbuf + S1_B + kb);
            }
            #pragma unroll
            for (int j = 0; j < 4; j++) {
                mma_f16(acc[j], ah, b + 2 * j);
                mma_f16(acc[j], al, b + 2 * j);
            }
        }

        if (c + 1 < NCHUNK) store_s((c + 1) & 1);
        __syncthreads();
    }

    // ---- epilogue: T f32 -> gmem ----
    const int g = lane >> 2, tig = lane & 3;
    #pragma unroll
    for (int j = 0; j < 4; j++) {
        int col  = wn * 32 + j * 8 + tig * 2;
        int row0 = m0 + wm * 16 + g;
        *(float2*)(g_T + (size_t)row0 * RANK + col) =
            make_float2(acc[j][0], acc[j][1]);
        *(float2*)(g_T + (size_t)(row0 + 8) * RANK + col) =
            make_float2(acc[j][2], acc[j][3]);
    }
}

// ========================================================================
// Kernel 2: y = T @ U^T + bias   CTA tile [128 M][128 N], K=64
// T split fp16 hi/lo inline (2 products), U single fp16 inline.
// grid 2048, 8 warps, warp tile 32 M x 64 N.
// ========================================================================
static constexpr int SM2_THI  = 0;
static constexpr int SM2_TLO  = 16384;
static constexpr int SM2_U    = 32768;
static constexpr int SM2_BIAS = 49152;
static constexpr int SM2_TOTAL = 49152 + 512;

__global__ void __launch_bounds__(256) k2_gemm2(const float* __restrict__ U,
                                                const float* __restrict__ bias,
                                                float* __restrict__ y) {
    extern __shared__ char smem[];
    const uint32_t sb = smem_u32(smem);
    const int tid  = threadIdx.x;
    const int lane = tid & 31;
    const int wid  = tid >> 5;
    const int wm   = wid >> 1;       // 0..3 (32-row slabs)
    const int wn   = wid & 1;        // 0..1 (64-col slabs)
    const int m0   = (blockIdx.x >> 5) * 128;
    const int n0   = (blockIdx.x & 31) * 128;

    // ---- load + split T [128m][64k] f32, U [128n][64k] f32 ----
    #pragma unroll
    for (int i = 0; i < 4; i++) {
        int idx = tid + i * 256;           // 0..1023
        int r = idx >> 3, g = idx & 7;     // 128 rows x 8 groups
        uint32_t sw = SWZ((uint32_t)(r * 128 + g * 16));
        {
            const float* tp = g_T + (size_t)(m0 + r) * RANK + g * 8;
            float4 t0 = *(const float4*)tp;
            float4 t1 = *(const float4*)(tp + 4);
            uint4 hi, lo;
            split8h(t0, t1, hi, lo);
            *(uint4*)(smem + SM2_THI + sw) = hi;
            *(uint4*)(smem + SM2_TLO + sw) = lo;
        }
        {
            const float* up = U + (size_t)(n0 + r) * RANK + g * 8;
            float4 u0 = __ldg((const float4*)up);
            float4 u1 = __ldg((const float4*)(up + 4));
            *(uint4*)(smem + SM2_U + sw) = pack8h(u0, u1);
        }
    }
    if (tid < 128) ((float*)(smem + SM2_BIAS))[tid] = bias[n0 + tid];
    __syncthreads();

    const int sub = lane >> 3, lr = lane & 7;
    uint32_t a_off[2], b_off[4];
    #pragma unroll
    for (int mt = 0; mt < 2; mt++)
        a_off[mt] = (uint32_t)((wm * 32 + mt * 16 + (sub & 1) * 8 + lr) * 128 + (sub >> 1) * 16);
    #pragma unroll
    for (int p = 0; p < 4; p++)
        b_off[p] = (uint32_t)((wn * 64 + (p * 2 + (sub >> 1)) * 8 + lr) * 128 + (sub & 1) * 16);

    float acc[2][8][4];
    #pragma unroll
    for (int mt = 0; mt < 2; mt++)
        #pragma unroll
        for (int j = 0; j < 8; j++)
            #pragma unroll
            for (int t = 0; t < 4; t++) acc[mt][j][t] = 0.0f;

    #pragma unroll
    for (int ks = 0; ks < 4; ks++) {
        uint32_t ah[2][4], al[2][4], b[16];
        #pragma unroll
        for (int mt = 0; mt < 2; mt++) {
            uint32_t ka = SWZ(a_off[mt] + ks * 32);
            ldmx4(ah[mt], sb + SM2_THI + ka);
            ldmx4(al[mt], sb + SM2_TLO + ka);
        }
        #pragma unroll
        for (int p = 0; p < 4; p++) {
            uint32_t kb = SWZ(b_off[p] + ks * 32);
            ldmx4(b + 4 * p, sb + SM2_U + kb);
        }
        #pragma unroll
        for (int mt = 0; mt < 2; mt++)
            #pragma unroll
            for (int j = 0; j < 8; j++) {
                mma_f16(acc[mt][j], ah[mt], b + 2 * j);
                mma_f16(acc[mt][j], al[mt], b + 2 * j);
            }
    }

    // ---- epilogue: +bias, direct STG.64 ----
    const int g = lane >> 2, tig = lane & 3;
    const float* sbias = (const float*)(smem + SM2_BIAS);
    #pragma unroll
    for (int mt = 0; mt < 2; mt++) {
        #pragma unroll
        for (int j = 0; j < 8; j++) {
            int colr = wn * 64 + j * 8 + tig * 2;
            float b0 = sbias[colr], b1 = sbias[colr + 1];
            int row = m0 + wm * 32 + mt * 16 + g;
            *(float2*)(y + (size_t)row * OUT_F + n0 + colr) =
                make_float2(acc[mt][j][0] + b0, acc[mt][j][1] + b1);
            *(float2*)(y + (size_t)(row + 8) * OUT_F + n0 + colr) =
                make_float2(acc[mt][j][2] + b0, acc[mt][j][3] + b1);
        }
    }
}

// ========================================================================
// launch
// ========================================================================
extern "C" void kernel_launch(void* const* d_in, const int* in_sizes, int n_in,
                              void* d_out, int out_size) {
    const float* x    = (const float*)d_in[0];
    const float* U    = (const float*)d_in[1];
    const float* V    = (const float*)d_in[2];
    const float* bias = (const float*)d_in[3];
    float* y = (float*)d_out;

    cudaFuncSetAttribute(k1_gemm1, cudaFuncAttributeMaxDynamicSharedMemorySize, SM1_TOTAL);
    cudaFuncSetAttribute(k2_gemm2, cudaFuncAttributeMaxDynamicSharedMemorySize, SM2_TOTAL);

    k1_gemm1<<<M_TOTAL / 64, 256, SM1_TOTAL>>>(x, V);
    k2_gemm2<<<(M_TOTAL / 128) * (OUT_F / 128), 256, SM2_TOTAL>>>(U, bias, y);
}

// round 4
// speedup vs baseline: 1.3653x; 1.2555x over previous
#include <cuda_runtime.h>
#include <cuda_fp16.h>
#include <cstdint>

#define M_TOTAL 8192
#define IN_F    4096
#define OUT_F   4096
#define RANK    64

// ---------------- device scratch ----------------
__device__ __align__(16) __half g_T[M_TOTAL * RANK];  // [8192][64] fp16
__device__ __align__(16) __half g_U[OUT_F * RANK];    // [4096][64] fp16
__device__ __align__(16) __half g_V[IN_F * RANK];     // [4096][64] fp16

// ---------------- helpers ----------------
__device__ __forceinline__ uint32_t smem_u32(const void* p) {
    uint32_t a;
    asm("{ .reg .u64 t; cvta.to.shared.u64 t, %1; cvt.u32.u64 %0, t; }" : "=r"(a) : "l"(p));
    return a;
}
#define SWZ(o) ((o) ^ (((o) >> 3) & 0x70))

__device__ __forceinline__ void cpasync16(uint32_t dst, const void* src) {
    asm volatile("cp.async.cg.shared.global [%0], [%1], 16;"
                 :: "r"(dst), "l"(__cvta_generic_to_global(src)) : "memory");
}
#define CP_COMMIT() asm volatile("cp.async.commit_group;" ::: "memory")
#define CP_WAIT0()  asm volatile("cp.async.wait_group 0;" ::: "memory")

__device__ __forceinline__ void ldmx4(uint32_t* r, uint32_t addr) {
    asm volatile("ldmatrix.sync.aligned.m8n8.x4.shared.b16 {%0,%1,%2,%3}, [%4];"
                 : "=r"(r[0]), "=r"(r[1]), "=r"(r[2]), "=r"(r[3]) : "r"(addr));
}
__device__ __forceinline__ void ldmx4t(uint32_t* r, uint32_t addr) {
    asm volatile("ldmatrix.sync.aligned.m8n8.x4.trans.shared.b16 {%0,%1,%2,%3}, [%4];"
                 : "=r"(r[0]), "=r"(r[1]), "=r"(r[2]), "=r"(r[3]) : "r"(addr));
}
__device__ __forceinline__ void mma_f16(float* d, const uint32_t* a, const uint32_t* b) {
    asm volatile(
        "mma.sync.aligned.m16n8k16.row.col.f32.f16.f16.f32 "
        "{%0,%1,%2,%3}, {%4,%5,%6,%7}, {%8,%9}, {%0,%1,%2,%3};"
        : "+f"(d[0]), "+f"(d[1]), "+f"(d[2]), "+f"(d[3])
        : "r"(a[0]), "r"(a[1]), "r"(a[2]), "r"(a[3]), "r"(b[0]), "r"(b[1]));
}
__device__ __forceinline__ uint4 pack8h(const float4& a, const float4& b) {
    __half2 h0 = __floats2half2_rn(a.x, a.y);
    __half2 h1 = __floats2half2_rn(a.z, a.w);
    __half2 h2 = __floats2half2_rn(b.x, b.y);
    __half2 h3 = __floats2half2_rn(b.z, b.w);
    return make_uint4(*(uint32_t*)&h0, *(uint32_t*)&h1, *(uint32_t*)&h2, *(uint32_t*)&h3);
}

// ========================================================================
// Kernel 0: convert U, V -> fp16 (same [4096][64] layout)
// ========================================================================
__global__ void __launch_bounds__(256) k0_prep(const float* __restrict__ U,
                                               const float* __restrict__ V) {
    int t = blockIdx.x * 256 + threadIdx.x;      // 0..32767
    size_t off = (size_t)t * 8;
    {
        float4 a = __ldg((const float4*)(U + off));
        float4 b = __ldg((const float4*)(U + off + 4));
        *(uint4*)(g_U + off) = pack8h(a, b);
    }
    {
        float4 a = __ldg((const float4*)(V + off));
        float4 b = __ldg((const float4*)(V + off + 4));
        *(uint4*)(g_V + off) = pack8h(a, b);
    }
}

// ========================================================================
// Kernel 1: T = x @ V   CTA [64M,64N], K=4096, grid 128, 16 warps (512 thr)
// x -> fp16 single product; V fp16 via cp.async; warp tile 16x16.
// ========================================================================
static constexpr int S1_A = 0, S1_B = 8192;
static constexpr int S1_STAGE = 16384;
static constexpr int SM1_TOTAL = 2 * S1_STAGE;   // 32768

__global__ void __launch_bounds__(512) k1_gemm1(const float* __restrict__ x) {
    extern __shared__ char smem[];
    const uint32_t sb = smem_u32(smem);
    const int tid  = threadIdx.x;
    const int lane = tid & 31;
    const int wid  = tid >> 5;       // 0..15
    const int wm   = wid & 3;        // 16-row slab
    const int wn   = wid >> 2;       // 16-col slab
    const int m0   = blockIdx.x * 64;

    const int sub = lane >> 3, lr = lane & 7;
    const uint32_t a_off  = (uint32_t)((wm * 16 + (sub & 1) * 8 + lr) * 128 + (sub >> 1) * 16);
    const uint32_t bt_off = (uint32_t)(((sub & 1) * 8 + lr) * 128 + wn * 32 + (sub >> 1) * 16);

    const int r = tid >> 3, g = tid & 7;    // 64 rows x 8 col-groups
    const float* xs = x + (size_t)(m0 + r) * IN_F + g * 8;
    const char*  vs = (const char*)g_V + (size_t)r * 128 + g * 16;
    const uint32_t sts_off = SWZ((uint32_t)(r * 128 + g * 16));

    float acc[2][4];
    #pragma unroll
    for (int j = 0; j < 2; j++)
        #pragma unroll
        for (int t = 0; t < 4; t++) acc[j][t] = 0.0f;

    float4 xa0, xa1;

    // prologue: chunk 0
    cpasync16(sb + S1_B + sts_off, vs);
    CP_COMMIT();
    xa0 = __ldg((const float4*)xs);
    xa1 = __ldg((const float4*)(xs + 4));
    *(uint4*)(smem + S1_A + sts_off) = pack8h(xa0, xa1);
    CP_WAIT0();
    __syncthreads();

    const int NCHUNK = IN_F / 64;    // 64
    for (int c = 0; c < NCHUNK; c++) {
        const int buf = c & 1;
        const int nbuf = buf ^ 1;

        if (c + 1 < NCHUNK) {
            cpasync16(sb + nbuf * S1_STAGE + S1_B + sts_off, vs + (size_t)(c + 1) * 64 * 128);
            CP_COMMIT();
            xa0 = __ldg((const float4*)(xs + (size_t)(c + 1) * 64));
            xa1 = __ldg((const float4*)(xs + (size_t)(c + 1) * 64 + 4));
        }

        const uint32_t sbuf = sb + buf * S1_STAGE;
        #pragma unroll
        for (int ks = 0; ks < 4; ks++) {
            uint32_t a[4], b[4];
            ldmx4(a, sbuf + S1_A + SWZ(a_off + ks * 32));
            ldmx4t(b, sbuf + S1_B + SWZ(bt_off + ks * 16 * 128));
            mma_f16(acc[0], a, b);
            mma_f16(acc[1], a, b + 2);
        }

        if (c + 1 < NCHUNK) {
            *(uint4*)(smem + nbuf * S1_STAGE + S1_A + sts_off) = pack8h(xa0, xa1);
            CP_WAIT0();
        }
        __syncthreads();
    }

    // ---- epilogue: acc -> fp16 -> g_T ----
    const int gq = lane >> 2, tig = lane & 3;
    #pragma unroll
    for (int j = 0; j < 2; j++) {
        int col  = wn * 16 + j * 8 + tig * 2;
        int row0 = m0 + wm * 16 + gq;
        *(__half2*)(g_T + (size_t)row0 * RANK + col) =
            __floats2half2_rn(acc[j][0], acc[j][1]);
        *(__half2*)(g_T + (size_t)(row0 + 8) * RANK + col) =
            __floats2half2_rn(acc[j][2], acc[j][3]);
    }
}

// ========================================================================
// Kernel 2: y = T @ U^T + bias   CTA [128M,128N], K=64, grid 2048, 8 warps
// T, U already fp16: pure cp.async prologue; single product.
// ========================================================================
static constexpr int SM2_T    = 0;
static constexpr int SM2_U    = 16384;
static constexpr int SM2_BIAS = 32768;
static constexpr int SM2_TOTAL = 32768 + 512;

__global__ void __launch_bounds__(256) k2_gemm2(const float* __restrict__ bias,
                                                float* __restrict__ y) {
    extern __shared__ char smem[];
    const uint32_t sb = smem_u32(smem);
    const int tid  = threadIdx.x;
    const int lane = tid & 31;
    const int wid  = tid >> 5;
    const int wm   = wid >> 1;       // 0..3 (32-row slabs)
    const int wn   = wid & 1;        // 0..1 (64-col slabs)
    const int m0   = (blockIdx.x >> 5) * 128;
    const int n0   = (blockIdx.x & 31) * 128;

    // ---- prologue: cp.async T[128][64] + U[128][64] fp16 ----
    #pragma unroll
    for (int i = 0; i < 4; i++) {
        int idx = tid + i * 256;          // 0..1023
        int r = idx >> 3, g = idx & 7;    // 128 rows x 8 groups
        uint32_t sw = SWZ((uint32_t)(r * 128 + g * 16));
        cpasync16(sb + SM2_T + sw, (const char*)g_T + (size_t)(m0 + r) * 128 + g * 16);
        cpasync16(sb + SM2_U + sw, (const char*)g_U + (size_t)(n0 + r) * 128 + g * 16);
    }
    if (tid < 32) {
        float4 bv = __ldg((const float4*)(bias + n0 + tid * 4));
        *(float4*)(smem + SM2_BIAS + tid * 16) = bv;
    }
    CP_COMMIT();
    CP_WAIT0();
    __syncthreads();

    const int sub = lane >> 3, lr = lane & 7;
    uint32_t a_off[2], b_off[4];
    #pragma unroll
    for (int mt = 0; mt < 2; mt++)
        a_off[mt] = (uint32_t)((wm * 32 + mt * 16 + (sub & 1) * 8 + lr) * 128 + (sub >> 1) * 16);
    #pragma unroll
    for (int p = 0; p < 4; p++)
        b_off[p] = (uint32_t)((wn * 64 + (p * 2 + (sub >> 1)) * 8 + lr) * 128 + (sub & 1) * 16);

    float acc[2][8][4];
    #pragma unroll
    for (int mt = 0; mt < 2; mt++)
        #pragma unroll
        for (int j = 0; j < 8; j++)
            #pragma unroll
            for (int t = 0; t < 4; t++) acc[mt][j][t] = 0.0f;

    #pragma unroll
    for (int ks = 0; ks < 4; ks++) {
        uint32_t a[2][4], b[16];
        #pragma unroll
        for (int mt = 0; mt < 2; mt++)
            ldmx4(a[mt], sb + SM2_T + SWZ(a_off[mt] + ks * 32));
        #pragma unroll
        for (int p = 0; p < 4; p++)
            ldmx4(b + 4 * p, sb + SM2_U + SWZ(b_off[p] + ks * 32));
        #pragma unroll
        for (int mt = 0; mt < 2; mt++)
            #pragma unroll
            for (int j = 0; j < 8; j++)
                mma_f16(acc[mt][j], a[mt], b + 2 * j);
    }

    // ---- epilogue: +bias, direct STG.64 ----
    const int gq = lane >> 2, tig = lane & 3;
    const float* sbias = (const float*)(smem + SM2_BIAS);
    #pragma unroll
    for (int mt = 0; mt < 2; mt++) {
        #pragma unroll
        for (int j = 0; j < 8; j++) {
            int colr = wn * 64 + j * 8 + tig * 2;
            float b0 = sbias[colr], b1 = sbias[colr + 1];
            int row = m0 + wm * 32 + mt * 16 + gq;
            *(float2*)(y + (size_t)row * OUT_F + n0 + colr) =
                make_float2(acc[mt][j][0] + b0, acc[mt][j][1] + b1);
            *(float2*)(y + (size_t)(row + 8) * OUT_F + n0 + colr) =
                make_float2(acc[mt][j][2] + b0, acc[mt][j][3] + b1);
        }
    }
}

// ========================================================================
// launch
// ========================================================================
extern "C" void kernel_launch(void* const* d_in, const int* in_sizes, int n_in,
                              void* d_out, int out_size) {
    const float* x    = (const float*)d_in[0];
    const float* U    = (const float*)d_in[1];
    const float* V    = (const float*)d_in[2];
    const float* bias = (const float*)d_in[3];
    float* y = (float*)d_out;

    cudaFuncSetAttribute(k1_gemm1, cudaFuncAttributeMaxDynamicSharedMemorySize, SM1_TOTAL);
    cudaFuncSetAttribute(k2_gemm2, cudaFuncAttributeMaxDynamicSharedMemorySize, SM2_TOTAL);

    k0_prep<<<128, 256>>>(U, V);
    k1_gemm1<<<M_TOTAL / 64, 512, SM1_TOTAL>>>(x);
    k2_gemm2<<<(M_TOTAL / 128) * (OUT_F / 128), 256, SM2_TOTAL>>>(bias, y);
}

// round 5
// speedup vs baseline: 1.7542x; 1.2848x over previous
#include <cuda_runtime.h>
#include <cuda_fp16.h>
#include <cstdint>

#define M_TOTAL 8192
#define IN_F    4096
#define OUT_F   4096
#define RANK    64
#define KSPLIT  4

// ---------------- device scratch ----------------
__device__ __align__(16) __half g_Tp[KSPLIT * M_TOTAL * RANK]; // partials fp16
__device__ __align__(16) __half g_T[M_TOTAL * RANK];           // reduced fp16
__device__ __align__(16) __half g_U[OUT_F * RANK];             // fp16
__device__ __align__(16) __half g_V[IN_F * RANK];              // fp16

// ---------------- helpers ----------------
__device__ __forceinline__ uint32_t smem_u32(const void* p) {
    uint32_t a;
    asm("{ .reg .u64 t; cvta.to.shared.u64 t, %1; cvt.u32.u64 %0, t; }" : "=r"(a) : "l"(p));
    return a;
}
#define SWZ(o) ((o) ^ (((o) >> 3) & 0x70))

__device__ __forceinline__ void cpasync16(uint32_t dst, const void* src) {
    asm volatile("cp.async.cg.shared.global [%0], [%1], 16;"
                 :: "r"(dst), "l"(__cvta_generic_to_global(src)) : "memory");
}
#define CP_COMMIT() asm volatile("cp.async.commit_group;" ::: "memory")
#define CP_WAIT0()  asm volatile("cp.async.wait_group 0;" ::: "memory")

__device__ __forceinline__ void ldmx4(uint32_t* r, uint32_t addr) {
    asm volatile("ldmatrix.sync.aligned.m8n8.x4.shared.b16 {%0,%1,%2,%3}, [%4];"
                 : "=r"(r[0]), "=r"(r[1]), "=r"(r[2]), "=r"(r[3]) : "r"(addr));
}
__device__ __forceinline__ void ldmx4t(uint32_t* r, uint32_t addr) {
    asm volatile("ldmatrix.sync.aligned.m8n8.x4.trans.shared.b16 {%0,%1,%2,%3}, [%4];"
                 : "=r"(r[0]), "=r"(r[1]), "=r"(r[2]), "=r"(r[3]) : "r"(addr));
}
__device__ __forceinline__ void mma_f16(float* d, const uint32_t* a, const uint32_t* b) {
    asm volatile(
        "mma.sync.aligned.m16n8k16.row.col.f32.f16.f16.f32 "
        "{%0,%1,%2,%3}, {%4,%5,%6,%7}, {%8,%9}, {%0,%1,%2,%3};"
        : "+f"(d[0]), "+f"(d[1]), "+f"(d[2]), "+f"(d[3])
        : "r"(a[0]), "r"(a[1]), "r"(a[2]), "r"(a[3]), "r"(b[0]), "r"(b[1]));
}
__device__ __forceinline__ uint4 pack8h(const float4& a, const float4& b) {
    __half2 h0 = __floats2half2_rn(a.x, a.y);
    __half2 h1 = __floats2half2_rn(a.z, a.w);
    __half2 h2 = __floats2half2_rn(b.x, b.y);
    __half2 h3 = __floats2half2_rn(b.z, b.w);
    return make_uint4(*(uint32_t*)&h0, *(uint32_t*)&h1, *(uint32_t*)&h2, *(uint32_t*)&h3);
}

// ========================================================================
// Kernel 0: convert U, V -> fp16 ([4096][64] layout). 65536 threads.
// ========================================================================
__global__ void __launch_bounds__(256) k0_prep(const float* __restrict__ U,
                                               const float* __restrict__ V) {
    int t = blockIdx.x * 256 + threadIdx.x;      // 0..65535
    size_t off = (size_t)t * 4;
    {
        float4 a = __ldg((const float4*)(U + off));
        __half2 h0 = __floats2half2_rn(a.x, a.y);
        __half2 h1 = __floats2half2_rn(a.z, a.w);
        *(uint2*)(g_U + off) = make_uint2(*(uint32_t*)&h0, *(uint32_t*)&h1);
    }
    {
        float4 a = __ldg((const float4*)(V + off));
        __half2 h0 = __floats2half2_rn(a.x, a.y);
        __half2 h1 = __floats2half2_rn(a.z, a.w);
        *(uint2*)(g_V + off) = make_uint2(*(uint32_t*)&h0, *(uint32_t*)&h1);
    }
}

// ========================================================================
// Kernel 1: Tp[s] = x[:, s*1024:(s+1)*1024] @ V[s*1024:...]
// CTA [64M,64N], K=1024 per split, grid 512 (128 mtiles x 4 splits),
// 512 threads, warp tile 16x16, double-buffered.
// ========================================================================
static constexpr int S1_A = 0, S1_B = 8192;
static constexpr int S1_STAGE = 16384;
static constexpr int SM1_TOTAL = 2 * S1_STAGE;   // 32768

__global__ void __launch_bounds__(512) k1_gemm1(const float* __restrict__ x) {
    extern __shared__ char smem[];
    const uint32_t sb = smem_u32(smem);
    const int tid  = threadIdx.x;
    const int lane = tid & 31;
    const int wid  = tid >> 5;       // 0..15
    const int wm   = wid & 3;        // 16-row slab
    const int wn   = wid >> 2;       // 16-col slab
    const int mt   = blockIdx.x >> 2;          // 0..127
    const int ksp  = blockIdx.x & 3;           // 0..3
    const int m0   = mt * 64;
    const int k0   = ksp * (IN_F / KSPLIT);    // 0,1024,2048,3072

    const int sub = lane >> 3, lr = lane & 7;
    const uint32_t a_off  = (uint32_t)((wm * 16 + (sub & 1) * 8 + lr) * 128 + (sub >> 1) * 16);
    const uint32_t bt_off = (uint32_t)(((sub & 1) * 8 + lr) * 128 + wn * 32 + (sub >> 1) * 16);

    const int r = tid >> 3, g = tid & 7;    // 64 rows x 8 col-groups
    const float* xs = x + (size_t)(m0 + r) * IN_F + k0 + g * 8;
    const char*  vs = (const char*)g_V + (size_t)(k0 + r) * 128 + g * 16;
    const uint32_t sts_off = SWZ((uint32_t)(r * 128 + g * 16));

    float acc[2][4];
    #pragma unroll
    for (int j = 0; j < 2; j++)
        #pragma unroll
        for (int t = 0; t < 4; t++) acc[j][t] = 0.0f;

    float4 xa0, xa1;

    // prologue: chunk 0
    cpasync16(sb + S1_B + sts_off, vs);
    CP_COMMIT();
    xa0 = __ldg((const float4*)xs);
    xa1 = __ldg((const float4*)(xs + 4));
    *(uint4*)(smem + S1_A + sts_off) = pack8h(xa0, xa1);
    CP_WAIT0();
    __syncthreads();

    const int NCHUNK = (IN_F / KSPLIT) / 64;    // 16
    for (int c = 0; c < NCHUNK; c++) {
        const int buf = c & 1;
        const int nbuf = buf ^ 1;

        if (c + 1 < NCHUNK) {
            cpasync16(sb + nbuf * S1_STAGE + S1_B + sts_off, vs + (size_t)(c + 1) * 64 * 128);
            CP_COMMIT();
            xa0 = __ldg((const float4*)(xs + (size_t)(c + 1) * 64));
            xa1 = __ldg((const float4*)(xs + (size_t)(c + 1) * 64 + 4));
        }

        const uint32_t sbuf = sb + buf * S1_STAGE;
        #pragma unroll
        for (int ks = 0; ks < 4; ks++) {
            uint32_t a[4], b[4];
            ldmx4(a, sbuf + S1_A + SWZ(a_off + ks * 32));
            ldmx4t(b, sbuf + S1_B + SWZ(bt_off + ks * 16 * 128));
            mma_f16(acc[0], a, b);
            mma_f16(acc[1], a, b + 2);
        }

        if (c + 1 < NCHUNK) {
            *(uint4*)(smem + nbuf * S1_STAGE + S1_A + sts_off) = pack8h(xa0, xa1);
            CP_WAIT0();
        }
        __syncthreads();
    }

    // ---- epilogue: acc -> fp16 -> g_Tp[ksp] ----
    __half* Tp = g_Tp + (size_t)ksp * (M_TOTAL * RANK);
    const int gq = lane >> 2, tig = lane & 3;
    #pragma unroll
    for (int j = 0; j < 2; j++) {
        int col  = wn * 16 + j * 8 + tig * 2;
        int row0 = m0 + wm * 16 + gq;
        *(__half2*)(Tp + (size_t)row0 * RANK + col) =
            __floats2half2_rn(acc[j][0], acc[j][1]);
        *(__half2*)(Tp + (size_t)(row0 + 8) * RANK + col) =
            __floats2half2_rn(acc[j][2], acc[j][3]);
    }
}

// ========================================================================
// Kernel 1r: g_T = sum_s g_Tp[s]   (f32 accumulate, fp16 out)
// 65536 threads, 8 halves each.
// ========================================================================
__global__ void __launch_bounds__(256) k1_reduce() {
    int t = blockIdx.x * 256 + threadIdx.x;      // 0..65535
    size_t off = (size_t)t * 8;
    float2 s[4] = {{0,0},{0,0},{0,0},{0,0}};
    #pragma unroll
    for (int p = 0; p < KSPLIT; p++) {
        uint4 v = *(const uint4*)(g_Tp + (size_t)p * (M_TOTAL * RANK) + off);
        const __half2* h = (const __half2*)&v;
        #pragma unroll
        for (int q = 0; q < 4; q++) {
            float2 f = __half22float2(h[q]);
            s[q].x += f.x; s[q].y += f.y;
        }
    }
    __half2 o0 = __floats2half2_rn(s[0].x, s[0].y);
    __half2 o1 = __floats2half2_rn(s[1].x, s[1].y);
    __half2 o2 = __floats2half2_rn(s[2].x, s[2].y);
    __half2 o3 = __floats2half2_rn(s[3].x, s[3].y);
    *(uint4*)(g_T + off) = make_uint4(*(uint32_t*)&o0, *(uint32_t*)&o1,
                                      *(uint32_t*)&o2, *(uint32_t*)&o3);
}

// ========================================================================
// Kernel 2: y = T @ U^T + bias   CTA [128M,128N], K=64, grid 2048, 8 warps
// ========================================================================
static constexpr int SM2_T    = 0;
static constexpr int SM2_U    = 16384;
static constexpr int SM2_BIAS = 32768;
static constexpr int SM2_TOTAL = 32768 + 512;

__global__ void __launch_bounds__(256) k2_gemm2(const float* __restrict__ bias,
                                                float* __restrict__ y) {
    extern __shared__ char smem[];
    const uint32_t sb = smem_u32(smem);
    const int tid  = threadIdx.x;
    const int lane = tid & 31;
    const int wid  = tid >> 5;
    const int wm   = wid >> 1;       // 0..3 (32-row slabs)
    const int wn   = wid & 1;        // 0..1 (64-col slabs)
    const int m0   = (blockIdx.x >> 5) * 128;
    const int n0   = (blockIdx.x & 31) * 128;

    #pragma unroll
    for (int i = 0; i < 4; i++) {
        int idx = tid + i * 256;          // 0..1023
        int r = idx >> 3, g = idx & 7;    // 128 rows x 8 groups
        uint32_t sw = SWZ((uint32_t)(r * 128 + g * 16));
        cpasync16(sb + SM2_T + sw, (const char*)g_T + (size_t)(m0 + r) * 128 + g * 16);
        cpasync16(sb + SM2_U + sw, (const char*)g_U + (size_t)(n0 + r) * 128 + g * 16);
    }
    if (tid < 32) {
        float4 bv = __ldg((const float4*)(bias + n0 + tid * 4));
        *(float4*)(smem + SM2_BIAS + tid * 16) = bv;
    }
    CP_COMMIT();
    CP_WAIT0();
    __syncthreads();

    const int sub = lane >> 3, lr = lane & 7;
    uint32_t a_off[2], b_off[4];
    #pragma unroll
    for (int mt = 0; mt < 2; mt++)
        a_off[mt] = (uint32_t)((wm * 32 + mt * 16 + (sub & 1) * 8 + lr) * 128 + (sub >> 1) * 16);
    #pragma unroll
    for (int p = 0; p < 4; p++)
        b_off[p] = (uint32_t)((wn * 64 + (p * 2 + (sub >> 1)) * 8 + lr) * 128 + (sub & 1) * 16);

    float acc[2][8][4];
    #pragma unroll
    for (int mt = 0; mt < 2; mt++)
        #pragma unroll
        for (int j = 0; j < 8; j++)
            #pragma unroll
            for (int t = 0; t < 4; t++) acc[mt][j][t] = 0.0f;

    #pragma unroll
    for (int ks = 0; ks < 4; ks++) {
        uint32_t a[2][4], b[16];
        #pragma unroll
        for (int mt = 0; mt < 2; mt++)
            ldmx4(a[mt], sb + SM2_T + SWZ(a_off[mt] + ks * 32));
        #pragma unroll
        for (int p = 0; p < 4; p++)
            ldmx4(b + 4 * p, sb + SM2_U + SWZ(b_off[p] + ks * 32));
        #pragma unroll
        for (int mt = 0; mt < 2; mt++)
            #pragma unroll
            for (int j = 0; j < 8; j++)
                mma_f16(acc[mt][j], a[mt], b + 2 * j);
    }

    const int gq = lane >> 2, tig = lane & 3;
    const float* sbias = (const float*)(smem + SM2_BIAS);
    #pragma unroll
    for (int mt = 0; mt < 2; mt++) {
        #pragma unroll
        for (int j = 0; j < 8; j++) {
            int colr = wn * 64 + j * 8 + tig * 2;
            float b0 = sbias[colr], b1 = sbias[colr + 1];
            int row = m0 + wm * 32 + mt * 16 + gq;
            *(float2*)(y + (size_t)row * OUT_F + n0 + colr) =
                make_float2(acc[mt][j][0] + b0, acc[mt][j][1] + b1);
            *(float2*)(y + (size_t)(row + 8) * OUT_F + n0 + colr) =
                make_float2(acc[mt][j][2] + b0, acc[mt][j][3] + b1);
        }
    }
}

// ========================================================================
// launch
// ========================================================================
extern "C" void kernel_launch(void* const* d_in, const int* in_sizes, int n_in,
                              void* d_out, int out_size) {
    const float* x    = (const float*)d_in[0];
    const float* U    = (const float*)d_in[1];
    const float* V    = (const float*)d_in[2];
    const float* bias = (const float*)d_in[3];
    float* y = (float*)d_out;

    cudaFuncSetAttribute(k1_gemm1, cudaFuncAttributeMaxDynamicSharedMemorySize, SM1_TOTAL);
    cudaFuncSetAttribute(k2_gemm2, cudaFuncAttributeMaxDynamicSharedMemorySize, SM2_TOTAL);

    k0_prep<<<256, 256>>>(U, V);
    k1_gemm1<<<(M_TOTAL / 64) * KSPLIT, 512, SM1_TOTAL>>>(x);
    k1_reduce<<<256, 256>>>();
    k2_gemm2<<<(M_TOTAL / 128) * (OUT_F / 128), 256, SM2_TOTAL>>>(bias, y);
}